// round 1
// baseline (speedup 1.0000x reference)
#include <cuda_runtime.h>

// TT-embedding:
//   core0: (1, 8, 40, 16)   A[x][p][b]    idx = x*640 + p*16 + b     (5120 floats)
//   core1: (16, 8, 32, 16)  M[b][y][q][c] idx = b*4096 + y*512 + q*16 + c (65536)
//   core2: (16, 16, 25, 1)  C[c][z][r]    idx = c*400 + z*25 + r     (6400)
//   id -> p = id/800, q = (id/25)%32, r = id%25   (V = 40*32*25 = 32000)
//   out[tok][x*128 + y*16 + z] = sum_{b,c} A[x][p][b] M[b][y][q][c] C[c][z][r]
//
// Stage 1: t[qr][b][y*16+z] = sum_c M[b][y][q][c] * C[c][z][r]   (800 x 2048 table)
// Stage 2: out[tok][x][yz]  = sum_b A[x][p][b] * t[qr][b][yz]

#define NUM_QR   800
#define T_STRIDE 2048
#define NTOK     16384

__device__ float g_t[NUM_QR * T_STRIDE];   // 6.55 MB scratch (fits L2)
__device__ int   g_ids64;                  // 1 if ids buffer is int64, else int32

// ---------------------------------------------------------------------------
// Sniff id dtype: if ids are little-endian int64 (< 32000), every odd 32-bit
// word among the first 64 is zero. For int32 data those words are actual ids
// (uniform in [0,32000)), P(all 32 are zero) ~ 0.
// ---------------------------------------------------------------------------
__global__ void detect_id_width(const int* __restrict__ w) {
    int ored = 0;
#pragma unroll
    for (int i = 0; i < 32; ++i) ored |= w[2 * i + 1];
    g_ids64 = (ored == 0) ? 1 : 0;
}

// ---------------------------------------------------------------------------
// Stage 1: build t table. One block per (q,r) pair.
// ---------------------------------------------------------------------------
__global__ __launch_bounds__(256) void build_t(const float* __restrict__ c1,
                                               const float* __restrict__ c2) {
    int qr = blockIdx.x;
    int q = qr / 25;
    int r = qr - q * 25;

    __shared__ float s1[16 * 8 * 16];  // [b][y][c] -> b*128 + y*16 + c
    __shared__ float s2[16 * 16];      // [c][z]    -> c*16 + z

    int t = threadIdx.x;
    for (int i = t; i < 2048; i += 256) {
        int b = i >> 7, y = (i >> 4) & 7, c = i & 15;
        s1[i] = c1[b * 4096 + y * 512 + q * 16 + c];
    }
    if (t < 256) {
        int c = t >> 4, z = t & 15;
        s2[t] = c2[c * 400 + z * 25 + r];
    }
    __syncthreads();

    for (int o = t; o < 2048; o += 256) {
        int b = o >> 7;
        int yz = o & 127;
        int y = yz >> 4, z = yz & 15;
        float acc = 0.f;
#pragma unroll
        for (int c = 0; c < 16; ++c)
            acc += s1[b * 128 + y * 16 + c] * s2[c * 16 + z];
        g_t[qr * T_STRIDE + o] = acc;
    }
}

// ---------------------------------------------------------------------------
// Stage 2: per-token gather + rank-16 contraction. One warp per token.
// Lane l owns output columns yz in [4l, 4l+4) for all 8 x values.
// ---------------------------------------------------------------------------
__global__ __launch_bounds__(256) void tt_gather(const float* __restrict__ c0,
                                                 const int* __restrict__ ids,
                                                 float* __restrict__ out) {
    __shared__ float s0[5120];  // full core0
    int t = threadIdx.x;
    for (int i = t; i < 5120; i += 256) s0[i] = c0[i];
    __syncthreads();

    int warp = t >> 5;
    int lane = t & 31;
    int tok = blockIdx.x * 8 + warp;
    if (tok >= NTOK) return;

    int id = g_ids64 ? ids[2 * tok] : ids[tok];
    int p = id / 800;
    int qr = id - p * 800;

    const float* trow = g_t + qr * T_STRIDE + lane * 4;
    const float* a = s0 + p * 16;  // A[x][b] at a[x*640 + b]

    float4 acc[8];
#pragma unroll
    for (int x = 0; x < 8; ++x) acc[x] = make_float4(0.f, 0.f, 0.f, 0.f);

#pragma unroll
    for (int bb = 0; bb < 16; bb += 4) {
        float4 a4[8];
#pragma unroll
        for (int x = 0; x < 8; ++x)
            a4[x] = *reinterpret_cast<const float4*>(a + x * 640 + bb);

#pragma unroll
        for (int j = 0; j < 4; ++j) {
            float4 t4 = *reinterpret_cast<const float4*>(trow + (bb + j) * 128);
#pragma unroll
            for (int x = 0; x < 8; ++x) {
                float av = (j == 0) ? a4[x].x : (j == 1) ? a4[x].y
                          : (j == 2) ? a4[x].z : a4[x].w;
                acc[x].x = fmaf(av, t4.x, acc[x].x);
                acc[x].y = fmaf(av, t4.y, acc[x].y);
                acc[x].z = fmaf(av, t4.z, acc[x].z);
                acc[x].w = fmaf(av, t4.w, acc[x].w);
            }
        }
    }

    float4* op = reinterpret_cast<float4*>(out + (size_t)tok * 1024 + lane * 4);
#pragma unroll
    for (int x = 0; x < 8; ++x) op[x * 32] = acc[x];
}

// ---------------------------------------------------------------------------
extern "C" void kernel_launch(void* const* d_in, const int* in_sizes, int n_in,
                              void* d_out, int out_size) {
    const float* core0 = (const float*)d_in[0];
    const float* core1 = (const float*)d_in[1];
    const float* core2 = (const float*)d_in[2];
    const int*   ids   = (const int*)d_in[3];
    float* out = (float*)d_out;

    detect_id_width<<<1, 1>>>(ids);
    build_t<<<NUM_QR, 256>>>(core1, core2);
    tt_gather<<<NTOK / 8, 256>>>(core0, ids, out);
}